// round 15
// baseline (speedup 1.0000x reference)
#include <cuda_runtime.h>
#include <cuda_fp16.h>
#include <cstdint>
#include <math.h>

// Problem constants
#define B_BATCH 8
#define T_SEQ   2048
#define DIN     1024
#define DOUT    1024
#define M_TOTAL (B_BATCH * T_SEQ)   // 16384
#define GAMMA_F 0.9865f

// Scan chunking
#define NCH 64
#define CHUNK (T_SEQ / NCH)         // 32

// GEMM tiling: CTA 128x128, K-chunk 64, 4 warps (2x2), warp tile 64x64.
// Split kernels, half-grids (64 row-tiles each), 2 CTAs/SM.
#define KCHUNK 64
#define SMEM_STRIDE 72                        // fp16 elems/row (64+8 pad) = 144 B
#define A_OFF       0
#define B_OFF       18432
#define STAGE_BYTES 36864
#define NST 3
#define SMEM_TOTAL  (NST * STAGE_BYTES)       // 110592 (x2 CTAs = 221184 < 228KB)
#define NSTAGES 16                            // 16 k-chunks
#define NTHREADS 128

// ---------------- device scratch ----------------
__device__ float g_wksum[DIN];
__device__ float g_ksum[M_TOTAL];
__device__ float g_carry[B_BATCH][NCH][DIN];
__device__ __half g_q16[(size_t)M_TOTAL * DOUT]; // 32 MB fp16 Q scratch
__device__ __half g_xq_hi[(size_t)M_TOTAL * DIN];
__device__ __half g_sv_hi[(size_t)M_TOTAL * DIN];
__device__ __half g_wqt_hi[(size_t)DIN * DOUT];   // [n][k]
__device__ __half g_wvt_hi[(size_t)DIN * DOUT];

// ---------------- helpers ----------------
__device__ __forceinline__ uint32_t smem_u32(const void* p) {
    uint32_t a;
    asm("{ .reg .u64 t; cvta.to.shared.u64 t, %1; cvt.u32.u64 %0, t; }" : "=r"(a) : "l"(p));
    return a;
}
__device__ __forceinline__ void cp16(uint32_t dst, const void* src) {
    asm volatile("cp.async.cg.shared.global [%0], [%1], 16;\n" :: "r"(dst), "l"(src));
}
__device__ __forceinline__ void ldsm_x4(uint32_t* r, uint32_t addr) {
    asm volatile("ldmatrix.sync.aligned.m8n8.x4.shared.b16 {%0,%1,%2,%3}, [%4];"
                 : "=r"(r[0]), "=r"(r[1]), "=r"(r[2]), "=r"(r[3]) : "r"(addr));
}
__device__ __forceinline__ void mma_f16(float* c, const uint32_t* a, const uint32_t* b) {
    asm volatile(
        "mma.sync.aligned.m16n8k16.row.col.f32.f16.f16.f32 "
        "{%0,%1,%2,%3},{%4,%5,%6,%7},{%8,%9},{%0,%1,%2,%3};\n"
        : "+f"(c[0]), "+f"(c[1]), "+f"(c[2]), "+f"(c[3])
        : "r"(a[0]), "r"(a[1]), "r"(a[2]), "r"(a[3]), "r"(b[0]), "r"(b[1]));
}

// ---------------- kernel 1: wksum[d] = sum_e Wk[d][e] ----------------
__global__ void wksum_kernel(const float* __restrict__ Wk) {
    int d = blockIdx.x;
    float s = 0.f;
    for (int e = threadIdx.x; e < DOUT; e += 256)
        s += Wk[(size_t)d * DOUT + e];
    __shared__ float red[256];
    red[threadIdx.x] = s;
    __syncthreads();
    for (int o = 128; o > 0; o >>= 1) {
        if (threadIdx.x < o) red[threadIdx.x] += red[threadIdx.x + o];
        __syncthreads();
    }
    if (threadIdx.x == 0) g_wksum[d] = red[0];
}

// ---------------- W transpose -> fp16 (side stream) ----------------
__global__ void prep_w(const float* __restrict__ Wq,
                       const float* __restrict__ Wv) {
    int b = blockIdx.x;
    int tid = threadIdx.x;
    __shared__ float tile[32][33];
    const float* W = (b < 1024) ? Wq : Wv;
    __half* Th = (b < 1024) ? g_wqt_hi : g_wvt_hi;
    b &= 1023;
    int n0 = (b & 31) * 32, k0 = (b >> 5) * 32;
    int tx = tid & 31, ty = tid >> 5;
    for (int i = ty; i < 32; i += 8)
        tile[i][tx] = W[(size_t)(k0 + i) * DOUT + n0 + tx];
    __syncthreads();
    for (int i = ty; i < 32; i += 8)
        Th[(size_t)(n0 + i) * DIN + k0 + tx] = __float2half_rn(tile[tx][i]);
}

// ---------------- xq -> fp16, half at a time ----------------
__global__ void convA(const float* __restrict__ xq, int half) {
    size_t idx = (size_t)half * 8192 * 256 + (size_t)blockIdx.x * 256 + threadIdx.x;
    float4 v = ((const float4*)xq)[idx];
    __half h[4] = {__float2half_rn(v.x), __float2half_rn(v.y),
                   __float2half_rn(v.z), __float2half_rn(v.w)};
    ((uint2*)g_xq_hi)[idx] = *(uint2*)h;
}

// ---------------- merged ksum + per-chunk carries ----------------
__global__ void scan_carry(const float* __restrict__ xk,
                           const float* __restrict__ xv) {
    int ch = blockIdx.x, b = blockIdx.y;
    int t0 = ch * CHUNK;
    __shared__ float ks[CHUNK];
    int warp = threadIdx.x >> 5, lane = threadIdx.x & 31;

    #pragma unroll
    for (int rr = 0; rr < 4; rr++) {
        int t = warp * 4 + rr;
        const float4* row = (const float4*)(xk + ((size_t)b * T_SEQ + t0 + t) * DIN);
        const float4* wk = (const float4*)g_wksum;
        float s = 0.f;
        #pragma unroll
        for (int it = 0; it < 8; it++) {
            float4 a = row[lane + it * 32], w = wk[lane + it * 32];
            s += a.x * w.x + a.y * w.y + a.z * w.z + a.w * w.w;
        }
        #pragma unroll
        for (int o = 16; o; o >>= 1)
            s += __shfl_xor_sync(0xFFFFFFFFu, s, o);
        if (lane == 0) {
            float val = (t0 + t == 0) ? 0.f : s;
            ks[t] = val;
            g_ksum[b * T_SEQ + t0 + t] = val;
        }
    }
    __syncthreads();

    int d0 = threadIdx.x * 4;
    const float* base = xv + ((size_t)b * T_SEQ + t0) * DIN + d0;
    float s0 = 0.f, s1 = 0.f, s2 = 0.f, s3 = 0.f;
    #pragma unroll 8
    for (int t = 0; t < CHUNK; t++) {
        float4 v = *(const float4*)(base + (size_t)t * DIN);
        float k = ks[t];
        s0 = GAMMA_F * s0 + k * v.x;
        s1 = GAMMA_F * s1 + k * v.y;
        s2 = GAMMA_F * s2 + k * v.z;
        s3 = GAMMA_F * s3 + k * v.w;
    }
    *(float4*)&g_carry[b][ch][d0] = make_float4(s0, s1, s2, s3);
}

// ---------------- in-place exclusive prefix over chunk carries ----------------
__global__ void scan_mid(float gammaC) {
    int idx = blockIdx.x * 256 + threadIdx.x;    // 0..8191
    int b = idx >> 10, d = idx & 1023;
    float c[NCH];
    #pragma unroll
    for (int ch = 0; ch < NCH; ch++)
        c[ch] = g_carry[b][ch][d];
    float s = 0.f;
    #pragma unroll
    for (int ch = 0; ch < NCH; ch++) {
        float t = c[ch];
        c[ch] = s;
        s = s * gammaC + t;
    }
    #pragma unroll
    for (int ch = 0; ch < NCH; ch++)
        g_carry[b][ch][d] = c[ch];
}

// ---------------- apply prefix + write sv (fp16), 8 lanes/thread ----------------
__global__ void scan_apply(const float* __restrict__ xv) {
    int ch = blockIdx.x, b = blockIdx.y;
    int d0 = threadIdx.x * 8;
    float4 p0 = *(const float4*)&g_carry[b][ch][d0];
    float4 p1 = *(const float4*)&g_carry[b][ch][d0 + 4];
    float s0 = p0.x, s1 = p0.y, s2 = p0.z, s3 = p0.w;
    float s4 = p1.x, s5 = p1.y, s6 = p1.z, s7 = p1.w;
    size_t base_off = ((size_t)b * T_SEQ + (size_t)ch * CHUNK) * DIN + d0;
    const float* base = xv + base_off;
    const float* ks = g_ksum + b * T_SEQ + ch * CHUNK;
    #pragma unroll 4
    for (int t = 0; t < CHUNK; t++) {
        float4 v0 = *(const float4*)(base + (size_t)t * DIN);
        float4 v1 = *(const float4*)(base + (size_t)t * DIN + 4);
        float k = ks[t];
        s0 = GAMMA_F * s0 + k * v0.x;
        s1 = GAMMA_F * s1 + k * v0.y;
        s2 = GAMMA_F * s2 + k * v0.z;
        s3 = GAMMA_F * s3 + k * v0.w;
        s4 = GAMMA_F * s4 + k * v1.x;
        s5 = GAMMA_F * s5 + k * v1.y;
        s6 = GAMMA_F * s6 + k * v1.z;
        s7 = GAMMA_F * s7 + k * v1.w;
        __half h[8] = {__float2half_rn(s0), __float2half_rn(s1),
                       __float2half_rn(s2), __float2half_rn(s3),
                       __float2half_rn(s4), __float2half_rn(s5),
                       __float2half_rn(s6), __float2half_rn(s7)};
        *(uint4*)(g_sv_hi + base_off + (size_t)t * DIN) = *(uint4*)h;
    }
}

// ---------------- split GEMMs (CTA 128x128, 4 warps, warp tile 64x64) ----------------
// qgemm: g_q16 = fp16(xq@Wq).  sgemm: out = fp32(g_q16) .* (sv@Wv).

__device__ __forceinline__ void load_tile_f16(uint32_t sbase, const __half* g,
                                              int row0, int k0, int tid) {
    const char* gb = (const char*)(g + (size_t)row0 * DIN + k0);
    #pragma unroll
    for (int i = 0; i < 8; i++) {
        int slot = tid + i * NTHREADS;       // 0..1023
        int r = slot >> 3, c = slot & 7;     // 8 x 16B chunks per 128B row
        cp16(sbase + (uint32_t)(r * (SMEM_STRIDE * 2) + c * 16),
             gb + (size_t)r * (DIN * 2) + c * 16);
    }
}

__device__ __forceinline__ void mma_pass(uint32_t Abase, uint32_t Bbase,
                                         float acc[4][8][4], int wm, int wn, int lane) {
    const int arow = lane & 15;
    const int acol8 = (lane >> 4) * 8;
    const int bnrow = ((lane >> 4) & 1) * 8 + (lane & 7);
    const int bcol8 = ((lane >> 3) & 1) * 8;

    #pragma unroll
    for (int kk = 0; kk < KCHUNK; kk += 16) {
        uint32_t ah[4][4], bh[8][2];
        #pragma unroll
        for (int i = 0; i < 4; i++) {
            uint32_t aoff = (uint32_t)((wm * 64 + i * 16 + arow) * (SMEM_STRIDE * 2)
                                       + (kk + acol8) * 2);
            ldsm_x4(ah[i], Abase + aoff);
        }
        #pragma unroll
        for (int j0 = 0; j0 < 8; j0 += 2) {
            uint32_t boff = (uint32_t)((wn * 64 + j0 * 8 + bnrow) * (SMEM_STRIDE * 2)
                                       + (kk + bcol8) * 2);
            uint32_t br[4];
            ldsm_x4(br, Bbase + boff);
            bh[j0][0] = br[0]; bh[j0][1] = br[1];
            bh[j0 + 1][0] = br[2]; bh[j0 + 1][1] = br[3];
        }
        #pragma unroll
        for (int i = 0; i < 4; i++)
            #pragma unroll
            for (int j = 0; j < 8; j++)
                mma_f16(acc[i][j], ah[i], bh[j]);
    }
}

// MULT=0 -> write fp16 Q scratch; MULT=1 -> multiply by g_q16, write fp32 out
template <int MULT>
__device__ __forceinline__ void gemm_body(const __half* Aglob, const __half* Bglob,
                                          float* dst, int yoff) {
    extern __shared__ char smem[];
    uint32_t sb = smem_u32(smem);
    const int tid = threadIdx.x;
    const int warp = tid >> 5, lane = tid & 31;
    const int wm = warp >> 1, wn = warp & 1;
    const int g = lane >> 2, tg = lane & 3;
    const int row0 = (blockIdx.y + yoff) * 128;
    const int n0 = blockIdx.x * 128;

    float acc[4][8][4];
    #pragma unroll
    for (int i = 0; i < 4; i++)
        #pragma unroll
        for (int j = 0; j < 8; j++)
            #pragma unroll
            for (int k = 0; k < 4; k++) acc[i][j][k] = 0.f;

    auto issue = [&](int s) {
        if (s < NSTAGES) {
            int k0 = s * KCHUNK;
            uint32_t bufb = sb + (uint32_t)(s % NST) * STAGE_BYTES;
            load_tile_f16(bufb + A_OFF, Aglob, row0, k0, tid);
            load_tile_f16(bufb + B_OFF, Bglob, n0,  k0, tid);
        }
        asm volatile("cp.async.commit_group;\n" ::: "memory");
    };

    issue(0);
    issue(1);

    for (int s = 0; s < NSTAGES; s++) {
        asm volatile("cp.async.wait_group 1;\n" ::: "memory");
        __syncthreads();
        issue(s + 2);
        uint32_t bufb = sb + (uint32_t)(s % NST) * STAGE_BYTES;
        mma_pass(bufb + A_OFF, bufb + B_OFF, acc, wm, wn, lane);
    }

    #pragma unroll
    for (int i = 0; i < 4; i++) {
        #pragma unroll
        for (int j = 0; j < 8; j++) {
            int r = row0 + wm * 64 + i * 16;
            int c = n0 + wn * 64 + j * 8 + 2 * tg;
            size_t o0 = (size_t)(r + g    ) * DOUT + c;
            size_t o1 = (size_t)(r + g + 8) * DOUT + c;
            if (MULT) {
                __half2 q0 = *(const __half2*)(g_q16 + o0);
                __half2 q1 = *(const __half2*)(g_q16 + o1);
                float2 v0, v1;
                v0.x = acc[i][j][0] * __half2float(q0.x);
                v0.y = acc[i][j][1] * __half2float(q0.y);
                v1.x = acc[i][j][2] * __half2float(q1.x);
                v1.y = acc[i][j][3] * __half2float(q1.y);
                *(float2*)(dst + o0) = v0;
                *(float2*)(dst + o1) = v1;
            } else {
                __half2 h0, h1;
                h0.x = __float2half_rn(acc[i][j][0]);
                h0.y = __float2half_rn(acc[i][j][1]);
                h1.x = __float2half_rn(acc[i][j][2]);
                h1.y = __float2half_rn(acc[i][j][3]);
                *(__half2*)(g_q16 + o0) = h0;
                *(__half2*)(g_q16 + o1) = h1;
            }
        }
    }
}

__global__ __launch_bounds__(NTHREADS, 2) void qgemm(int yoff) {
    gemm_body<0>(g_xq_hi, g_wqt_hi, nullptr, yoff);
}
__global__ __launch_bounds__(NTHREADS, 2) void sgemm(float* __restrict__ out, int yoff) {
    gemm_body<1>(g_sv_hi, g_wvt_hi, out, yoff);
}

// ---------------- launch ----------------
extern "C" void kernel_launch(void* const* d_in, const int* in_sizes, int n_in,
                              void* d_out, int out_size)
{
    const float* xq = (const float*)d_in[0];
    const float* xk = (const float*)d_in[1];
    const float* xv = (const float*)d_in[2];
    const float* Wq = (const float*)d_in[3];
    const float* Wk = (const float*)d_in[4];
    const float* Wv = (const float*)d_in[5];
    float* out = (float*)d_out;

    float gammaC = (float)pow((double)GAMMA_F, (double)CHUNK);

    cudaFuncSetAttribute(qgemm, cudaFuncAttributeMaxDynamicSharedMemorySize, SMEM_TOTAL);
    cudaFuncSetAttribute(sgemm, cudaFuncAttributeMaxDynamicSharedMemorySize, SMEM_TOTAL);

    static cudaStream_t s2 = nullptr, s3 = nullptr;
    static cudaEvent_t evFork = nullptr, evW = nullptr, evC2 = nullptr,
                       evQ1 = nullptr, evQ2 = nullptr;
    if (s2 == nullptr) {
        cudaStreamCreateWithFlags(&s2, cudaStreamNonBlocking);
        cudaStreamCreateWithFlags(&s3, cudaStreamNonBlocking);
        cudaEventCreateWithFlags(&evFork, cudaEventDisableTiming);
        cudaEventCreateWithFlags(&evW, cudaEventDisableTiming);
        cudaEventCreateWithFlags(&evC2, cudaEventDisableTiming);
        cudaEventCreateWithFlags(&evQ1, cudaEventDisableTiming);
        cudaEventCreateWithFlags(&evQ2, cudaEventDisableTiming);
    }

    cudaEventRecord(evFork, 0);
    cudaStreamWaitEvent(s2, evFork, 0);
    cudaStreamWaitEvent(s3, evFork, 0);

    // s3: W transposes (needed by qgemm h1), then second half of xq conversion.
    prep_w<<<2048, 256, 0, s3>>>(Wq, Wv);
    cudaEventRecord(evW, s3);
    convA<<<8192, 256, 0, s3>>>(xq, 1);
    cudaEventRecord(evC2, s3);

    // s2: first half conversion -> qgemm h1 -> (wait conv h2) -> qgemm h2.
    convA<<<8192, 256, 0, s2>>>(xq, 0);
    cudaStreamWaitEvent(s2, evW, 0);
    qgemm<<<dim3(8, 64), NTHREADS, SMEM_TOTAL, s2>>>(0);
    cudaEventRecord(evQ1, s2);
    cudaStreamWaitEvent(s2, evC2, 0);
    qgemm<<<dim3(8, 64), NTHREADS, SMEM_TOTAL, s2>>>(64);
    cudaEventRecord(evQ2, s2);

    // Main stream: scan chain, then S-GEMM halves pipelined against qgemm.
    wksum_kernel<<<DIN, 256>>>(Wk);
    scan_carry<<<dim3(NCH, B_BATCH), 256>>>(xk, xv);
    scan_mid<<<32, 256>>>(gammaC);
    scan_apply<<<dim3(NCH, B_BATCH), 128>>>(xv);

    cudaStreamWaitEvent(0, evQ1, 0);
    sgemm<<<dim3(8, 64), NTHREADS, SMEM_TOTAL>>>(out, 0);   // overlaps qgemm h2
    cudaStreamWaitEvent(0, evQ2, 0);
    sgemm<<<dim3(8, 64), NTHREADS, SMEM_TOTAL>>>(out, 64);
}

// round 16
// speedup vs baseline: 1.1012x; 1.1012x over previous
#include <cuda_runtime.h>
#include <cuda_fp16.h>
#include <cstdint>
#include <math.h>

// Problem constants
#define B_BATCH 8
#define T_SEQ   2048
#define DIN     1024
#define DOUT    1024
#define M_TOTAL (B_BATCH * T_SEQ)   // 16384
#define GAMMA_F 0.9865f

// Scan chunking
#define NCH 64
#define CHUNK (T_SEQ / NCH)         // 32

// GEMM tiling: CTA 128x128, K-chunk 64, 8 warps (2x4), warp tile 64x32.
// Split kernels, quarter-grids (32 row-tiles each), 2 CTAs/SM.
#define KCHUNK 64
#define SMEM_STRIDE 72                        // fp16 elems/row (64+8 pad) = 144 B
#define A_OFF       0
#define B_OFF       18432
#define STAGE_BYTES 36864
#define NST 3
#define SMEM_TOTAL  (NST * STAGE_BYTES)       // 110592 (x2 CTAs = 221184 < 228KB)
#define NSTAGES 16                            // 16 k-chunks

// ---------------- device scratch ----------------
__device__ float g_wksum[DIN];
__device__ float g_ksum[M_TOTAL];
__device__ float g_carry[B_BATCH][NCH][DIN];
__device__ __half g_q16[(size_t)M_TOTAL * DOUT]; // 32 MB fp16 Q scratch
__device__ __half g_xq_hi[(size_t)M_TOTAL * DIN];
__device__ __half g_sv_hi[(size_t)M_TOTAL * DIN];
__device__ __half g_wqt_hi[(size_t)DIN * DOUT];   // [n][k]
__device__ __half g_wvt_hi[(size_t)DIN * DOUT];

// ---------------- helpers ----------------
__device__ __forceinline__ uint32_t smem_u32(const void* p) {
    uint32_t a;
    asm("{ .reg .u64 t; cvta.to.shared.u64 t, %1; cvt.u32.u64 %0, t; }" : "=r"(a) : "l"(p));
    return a;
}
__device__ __forceinline__ void cp16(uint32_t dst, const void* src) {
    asm volatile("cp.async.cg.shared.global [%0], [%1], 16;\n" :: "r"(dst), "l"(src));
}
__device__ __forceinline__ void ldsm_x4(uint32_t* r, uint32_t addr) {
    asm volatile("ldmatrix.sync.aligned.m8n8.x4.shared.b16 {%0,%1,%2,%3}, [%4];"
                 : "=r"(r[0]), "=r"(r[1]), "=r"(r[2]), "=r"(r[3]) : "r"(addr));
}
__device__ __forceinline__ void mma_f16(float* c, const uint32_t* a, const uint32_t* b) {
    asm volatile(
        "mma.sync.aligned.m16n8k16.row.col.f32.f16.f16.f32 "
        "{%0,%1,%2,%3},{%4,%5,%6,%7},{%8,%9},{%0,%1,%2,%3};\n"
        : "+f"(c[0]), "+f"(c[1]), "+f"(c[2]), "+f"(c[3])
        : "r"(a[0]), "r"(a[1]), "r"(a[2]), "r"(a[3]), "r"(b[0]), "r"(b[1]));
}

// ---------------- kernel 1: wksum[d] = sum_e Wk[d][e] ----------------
__global__ void wksum_kernel(const float* __restrict__ Wk) {
    int d = blockIdx.x;
    float s = 0.f;
    for (int e = threadIdx.x; e < DOUT; e += 256)
        s += Wk[(size_t)d * DOUT + e];
    __shared__ float red[256];
    red[threadIdx.x] = s;
    __syncthreads();
    for (int o = 128; o > 0; o >>= 1) {
        if (threadIdx.x < o) red[threadIdx.x] += red[threadIdx.x + o];
        __syncthreads();
    }
    if (threadIdx.x == 0) g_wksum[d] = red[0];
}

// ---------------- W transpose -> fp16 (side stream) ----------------
__global__ void prep_w(const float* __restrict__ Wq,
                       const float* __restrict__ Wv) {
    int b = blockIdx.x;
    int tid = threadIdx.x;
    __shared__ float tile[32][33];
    const float* W = (b < 1024) ? Wq : Wv;
    __half* Th = (b < 1024) ? g_wqt_hi : g_wvt_hi;
    b &= 1023;
    int n0 = (b & 31) * 32, k0 = (b >> 5) * 32;
    int tx = tid & 31, ty = tid >> 5;
    for (int i = ty; i < 32; i += 8)
        tile[i][tx] = W[(size_t)(k0 + i) * DOUT + n0 + tx];
    __syncthreads();
    for (int i = ty; i < 32; i += 8)
        Th[(size_t)(n0 + i) * DIN + k0 + tx] = __float2half_rn(tile[tx][i]);
}

// ---------------- xq -> fp16, quarter at a time ----------------
__global__ void convA(const float* __restrict__ xq, int quarter) {
    size_t idx = (size_t)quarter * 4096 * 256 + (size_t)blockIdx.x * 256 + threadIdx.x;
    float4 v = ((const float4*)xq)[idx];
    __half h[4] = {__float2half_rn(v.x), __float2half_rn(v.y),
                   __float2half_rn(v.z), __float2half_rn(v.w)};
    ((uint2*)g_xq_hi)[idx] = *(uint2*)h;
}

// ---------------- merged ksum + per-chunk carries ----------------
__global__ void scan_carry(const float* __restrict__ xk,
                           const float* __restrict__ xv) {
    int ch = blockIdx.x, b = blockIdx.y;
    int t0 = ch * CHUNK;
    __shared__ float ks[CHUNK];
    int warp = threadIdx.x >> 5, lane = threadIdx.x & 31;

    #pragma unroll
    for (int rr = 0; rr < 4; rr++) {
        int t = warp * 4 + rr;
        const float4* row = (const float4*)(xk + ((size_t)b * T_SEQ + t0 + t) * DIN);
        const float4* wk = (const float4*)g_wksum;
        float s = 0.f;
        #pragma unroll
        for (int it = 0; it < 8; it++) {
            float4 a = row[lane + it * 32], w = wk[lane + it * 32];
            s += a.x * w.x + a.y * w.y + a.z * w.z + a.w * w.w;
        }
        #pragma unroll
        for (int o = 16; o; o >>= 1)
            s += __shfl_xor_sync(0xFFFFFFFFu, s, o);
        if (lane == 0) {
            float val = (t0 + t == 0) ? 0.f : s;
            ks[t] = val;
            g_ksum[b * T_SEQ + t0 + t] = val;
        }
    }
    __syncthreads();

    int d0 = threadIdx.x * 4;
    const float* base = xv + ((size_t)b * T_SEQ + t0) * DIN + d0;
    float s0 = 0.f, s1 = 0.f, s2 = 0.f, s3 = 0.f;
    #pragma unroll 8
    for (int t = 0; t < CHUNK; t++) {
        float4 v = *(const float4*)(base + (size_t)t * DIN);
        float k = ks[t];
        s0 = GAMMA_F * s0 + k * v.x;
        s1 = GAMMA_F * s1 + k * v.y;
        s2 = GAMMA_F * s2 + k * v.z;
        s3 = GAMMA_F * s3 + k * v.w;
    }
    *(float4*)&g_carry[b][ch][d0] = make_float4(s0, s1, s2, s3);
}

// ---------------- in-place exclusive prefix over chunk carries ----------------
__global__ void scan_mid(float gammaC) {
    int idx = blockIdx.x * 256 + threadIdx.x;    // 0..8191
    int b = idx >> 10, d = idx & 1023;
    float c[NCH];
    #pragma unroll
    for (int ch = 0; ch < NCH; ch++)
        c[ch] = g_carry[b][ch][d];
    float s = 0.f;
    #pragma unroll
    for (int ch = 0; ch < NCH; ch++) {
        float t = c[ch];
        c[ch] = s;
        s = s * gammaC + t;
    }
    #pragma unroll
    for (int ch = 0; ch < NCH; ch++)
        g_carry[b][ch][d] = c[ch];
}

// ---------------- apply prefix + write sv (fp16), 8 lanes/thread ----------------
__global__ void scan_apply(const float* __restrict__ xv) {
    int ch = blockIdx.x, b = blockIdx.y;
    int d0 = threadIdx.x * 8;
    float4 p0 = *(const float4*)&g_carry[b][ch][d0];
    float4 p1 = *(const float4*)&g_carry[b][ch][d0 + 4];
    float s0 = p0.x, s1 = p0.y, s2 = p0.z, s3 = p0.w;
    float s4 = p1.x, s5 = p1.y, s6 = p1.z, s7 = p1.w;
    size_t base_off = ((size_t)b * T_SEQ + (size_t)ch * CHUNK) * DIN + d0;
    const float* base = xv + base_off;
    const float* ks = g_ksum + b * T_SEQ + ch * CHUNK;
    #pragma unroll 4
    for (int t = 0; t < CHUNK; t++) {
        float4 v0 = *(const float4*)(base + (size_t)t * DIN);
        float4 v1 = *(const float4*)(base + (size_t)t * DIN + 4);
        float k = ks[t];
        s0 = GAMMA_F * s0 + k * v0.x;
        s1 = GAMMA_F * s1 + k * v0.y;
        s2 = GAMMA_F * s2 + k * v0.z;
        s3 = GAMMA_F * s3 + k * v0.w;
        s4 = GAMMA_F * s4 + k * v1.x;
        s5 = GAMMA_F * s5 + k * v1.y;
        s6 = GAMMA_F * s6 + k * v1.z;
        s7 = GAMMA_F * s7 + k * v1.w;
        __half h[8] = {__float2half_rn(s0), __float2half_rn(s1),
                       __float2half_rn(s2), __float2half_rn(s3),
                       __float2half_rn(s4), __float2half_rn(s5),
                       __float2half_rn(s6), __float2half_rn(s7)};
        *(uint4*)(g_sv_hi + base_off + (size_t)t * DIN) = *(uint4*)h;
    }
}

// ---------------- split GEMMs (CTA 128x128, 8 warps, warp tile 64x32) ----------------
// qgemm: g_q16 = fp16(xq@Wq).  sgemm: out = fp32(g_q16) .* (sv@Wv).

__device__ __forceinline__ void load_tile_f16(uint32_t sbase, const __half* g,
                                              int row0, int k0, int tid) {
    const char* gb = (const char*)(g + (size_t)row0 * DIN + k0);
    #pragma unroll
    for (int i = 0; i < 4; i++) {
        int slot = tid + i * 256;            // 0..1023
        int r = slot >> 3, c = slot & 7;     // 8 x 16B chunks per 128B row
        cp16(sbase + (uint32_t)(r * (SMEM_STRIDE * 2) + c * 16),
             gb + (size_t)r * (DIN * 2) + c * 16);
    }
}

__device__ __forceinline__ void mma_pass(uint32_t Abase, uint32_t Bbase,
                                         float acc[4][4][4], int wm, int wn, int lane) {
    const int arow = lane & 15;
    const int acol8 = (lane >> 4) * 8;
    const int bnrow = ((lane >> 4) & 1) * 8 + (lane & 7);
    const int bcol8 = ((lane >> 3) & 1) * 8;

    #pragma unroll
    for (int kk = 0; kk < KCHUNK; kk += 16) {
        uint32_t ah[4][4], bh[4][2];
        #pragma unroll
        for (int i = 0; i < 4; i++) {
            uint32_t aoff = (uint32_t)((wm * 64 + i * 16 + arow) * (SMEM_STRIDE * 2)
                                       + (kk + acol8) * 2);
            ldsm_x4(ah[i], Abase + aoff);
        }
        #pragma unroll
        for (int j0 = 0; j0 < 4; j0 += 2) {
            uint32_t boff = (uint32_t)((wn * 32 + j0 * 8 + bnrow) * (SMEM_STRIDE * 2)
                                       + (kk + bcol8) * 2);
            uint32_t br[4];
            ldsm_x4(br, Bbase + boff);
            bh[j0][0] = br[0]; bh[j0][1] = br[1];
            bh[j0 + 1][0] = br[2]; bh[j0 + 1][1] = br[3];
        }
        #pragma unroll
        for (int i = 0; i < 4; i++)
            #pragma unroll
            for (int j = 0; j < 4; j++)
                mma_f16(acc[i][j], ah[i], bh[j]);
    }
}

// MULT=0 -> write fp16 Q scratch; MULT=1 -> multiply by g_q16, write fp32 out
template <int MULT>
__device__ __forceinline__ void gemm_body(const __half* Aglob, const __half* Bglob,
                                          float* dst, int yoff) {
    extern __shared__ char smem[];
    uint32_t sb = smem_u32(smem);
    const int tid = threadIdx.x;
    const int warp = tid >> 5, lane = tid & 31;
    const int wm = warp >> 2, wn = warp & 3;
    const int g = lane >> 2, tg = lane & 3;
    const int row0 = (blockIdx.y + yoff) * 128;
    const int n0 = blockIdx.x * 128;

    float acc[4][4][4];
    #pragma unroll
    for (int i = 0; i < 4; i++)
        #pragma unroll
        for (int j = 0; j < 4; j++)
            #pragma unroll
            for (int k = 0; k < 4; k++) acc[i][j][k] = 0.f;

    auto issue = [&](int s) {
        if (s < NSTAGES) {
            int k0 = s * KCHUNK;
            uint32_t bufb = sb + (uint32_t)(s % NST) * STAGE_BYTES;
            load_tile_f16(bufb + A_OFF, Aglob, row0, k0, tid);
            load_tile_f16(bufb + B_OFF, Bglob, n0,  k0, tid);
        }
        asm volatile("cp.async.commit_group;\n" ::: "memory");
    };

    issue(0);
    issue(1);

    for (int s = 0; s < NSTAGES; s++) {
        asm volatile("cp.async.wait_group 1;\n" ::: "memory");
        __syncthreads();
        issue(s + 2);
        uint32_t bufb = sb + (uint32_t)(s % NST) * STAGE_BYTES;
        mma_pass(bufb + A_OFF, bufb + B_OFF, acc, wm, wn, lane);
    }

    #pragma unroll
    for (int i = 0; i < 4; i++) {
        #pragma unroll
        for (int j = 0; j < 4; j++) {
            int r = row0 + wm * 64 + i * 16;
            int c = n0 + wn * 32 + j * 8 + 2 * tg;
            size_t o0 = (size_t)(r + g    ) * DOUT + c;
            size_t o1 = (size_t)(r + g + 8) * DOUT + c;
            if (MULT) {
                __half2 q0 = *(const __half2*)(g_q16 + o0);
                __half2 q1 = *(const __half2*)(g_q16 + o1);
                float2 v0, v1;
                v0.x = acc[i][j][0] * __half2float(q0.x);
                v0.y = acc[i][j][1] * __half2float(q0.y);
                v1.x = acc[i][j][2] * __half2float(q1.x);
                v1.y = acc[i][j][3] * __half2float(q1.y);
                *(float2*)(dst + o0) = v0;
                *(float2*)(dst + o1) = v1;
            } else {
                __half2 h0, h1;
                h0.x = __float2half_rn(acc[i][j][0]);
                h0.y = __float2half_rn(acc[i][j][1]);
                h1.x = __float2half_rn(acc[i][j][2]);
                h1.y = __float2half_rn(acc[i][j][3]);
                *(__half2*)(g_q16 + o0) = h0;
                *(__half2*)(g_q16 + o1) = h1;
            }
        }
    }
}

__global__ __launch_bounds__(256, 2) void qgemm(int yoff) {
    gemm_body<0>(g_xq_hi, g_wqt_hi, nullptr, yoff);
}
__global__ __launch_bounds__(256, 2) void sgemm(float* __restrict__ out, int yoff) {
    gemm_body<1>(g_sv_hi, g_wvt_hi, out, yoff);
}

// ---------------- launch ----------------
extern "C" void kernel_launch(void* const* d_in, const int* in_sizes, int n_in,
                              void* d_out, int out_size)
{
    const float* xq = (const float*)d_in[0];
    const float* xk = (const float*)d_in[1];
    const float* xv = (const float*)d_in[2];
    const float* Wq = (const float*)d_in[3];
    const float* Wk = (const float*)d_in[4];
    const float* Wv = (const float*)d_in[5];
    float* out = (float*)d_out;

    float gammaC = (float)pow((double)GAMMA_F, (double)CHUNK);

    cudaFuncSetAttribute(qgemm, cudaFuncAttributeMaxDynamicSharedMemorySize, SMEM_TOTAL);
    cudaFuncSetAttribute(sgemm, cudaFuncAttributeMaxDynamicSharedMemorySize, SMEM_TOTAL);

    static cudaStream_t s2 = nullptr, s3 = nullptr;
    static cudaEvent_t evFork = nullptr, evW = nullptr;
    static cudaEvent_t evC[4] = {nullptr, nullptr, nullptr, nullptr};
    static cudaEvent_t evQ[4] = {nullptr, nullptr, nullptr, nullptr};
    if (s2 == nullptr) {
        cudaStreamCreateWithFlags(&s2, cudaStreamNonBlocking);
        cudaStreamCreateWithFlags(&s3, cudaStreamNonBlocking);
        cudaEventCreateWithFlags(&evFork, cudaEventDisableTiming);
        cudaEventCreateWithFlags(&evW, cudaEventDisableTiming);
        for (int i = 0; i < 4; i++) {
            cudaEventCreateWithFlags(&evC[i], cudaEventDisableTiming);
            cudaEventCreateWithFlags(&evQ[i], cudaEventDisableTiming);
        }
    }

    cudaEventRecord(evFork, 0);
    cudaStreamWaitEvent(s2, evFork, 0);
    cudaStreamWaitEvent(s3, evFork, 0);

    // s3: W transposes (gate qgemm q0), then xq conversion quarters 1..3.
    prep_w<<<2048, 256, 0, s3>>>(Wq, Wv);
    cudaEventRecord(evW, s3);
    for (int q = 1; q < 4; q++) {
        convA<<<4096, 256, 0, s3>>>(xq, q);
        cudaEventRecord(evC[q], s3);
    }

    // s2: conv q0, then qgemm quarters as their conversions land.
    convA<<<4096, 256, 0, s2>>>(xq, 0);
    cudaStreamWaitEvent(s2, evW, 0);
    qgemm<<<dim3(8, 32), 256, SMEM_TOTAL, s2>>>(0);
    cudaEventRecord(evQ[0], s2);
    for (int q = 1; q < 4; q++) {
        cudaStreamWaitEvent(s2, evC[q], 0);
        qgemm<<<dim3(8, 32), 256, SMEM_TOTAL, s2>>>(q * 32);
        cudaEventRecord(evQ[q], s2);
    }

    // Main stream: scan chain, then sgemm quarters as their Q quarters land.
    wksum_kernel<<<DIN, 256>>>(Wk);
    scan_carry<<<dim3(NCH, B_BATCH), 256>>>(xk, xv);
    scan_mid<<<32, 256>>>(gammaC);
    scan_apply<<<dim3(NCH, B_BATCH), 128>>>(xv);

    for (int q = 0; q < 4; q++) {
        cudaStreamWaitEvent(0, evQ[q], 0);
        sgemm<<<dim3(8, 32), 256, SMEM_TOTAL>>>(out, q * 32);
    }
}